// round 1
// baseline (speedup 1.0000x reference)
#include <cuda_runtime.h>

// Haar DWT 2D, single level.
// Input:  x (B=32, C=3, H=512, W=512) float32
// Output: (B, C*4, 256, 256) float32, subband order [LL, LH, HL, HH]
//
// Each thread handles 4 output columns (8 input columns) of one output row
// for one (b,c): 4x LDG.128 in, 4x STG.128 out (one per subband).

#define B_ 32
#define C_ 3
#define H_ 512
#define W_ 512
#define HO (H_/2)   // 256
#define WO (W_/2)   // 256
#define QPW (WO/4)  // 64 col-quads per output row

__global__ __launch_bounds__(256, 8)
void haar_dwt2_kernel(const float* __restrict__ x, float* __restrict__ out) {
    int t = blockIdx.x * blockDim.x + threadIdx.x;
    // t decomposes as (bc, i, q): bc in [0,96), i in [0,256), q in [0,64)
    int q  = t & (QPW - 1);
    int i  = (t >> 6) & (HO - 1);
    int bc = t >> 14;                 // 6 + 8 bits consumed
    if (bc >= B_ * C_) return;

    const float* row0 = x + (size_t)bc * (H_ * W_) + (size_t)(2 * i) * W_ + 8 * q;
    const float* row1 = row0 + W_;

    float4 a0 = *(const float4*)(row0);      // cols 8q .. 8q+3, even row
    float4 a1 = *(const float4*)(row0 + 4);  // cols 8q+4 .. 8q+7, even row
    float4 b0 = *(const float4*)(row1);      // odd row
    float4 b1 = *(const float4*)(row1 + 4);

    // Per 2x2 block k (k=0..3): x00,x01 from even row; x10,x11 from odd row.
    // Block 0: a0.x a0.y / b0.x b0.y ; Block 1: a0.z a0.w / b0.z b0.w
    // Block 2: a1.x a1.y / b1.x b1.y ; Block 3: a1.z a1.w / b1.z b1.w
    float s0[4], d0[4], s1[4], d1[4];
    s0[0] = a0.x + a0.y;  d0[0] = a0.x - a0.y;  s1[0] = b0.x + b0.y;  d1[0] = b0.x - b0.y;
    s0[1] = a0.z + a0.w;  d0[1] = a0.z - a0.w;  s1[1] = b0.z + b0.w;  d1[1] = b0.z - b0.w;
    s0[2] = a1.x + a1.y;  d0[2] = a1.x - a1.y;  s1[2] = b1.x + b1.y;  d1[2] = b1.x - b1.y;
    s0[3] = a1.z + a1.w;  d0[3] = a1.z - a1.w;  s1[3] = b1.z + b1.w;  d1[3] = b1.z - b1.w;

    float4 LL, LH, HL, HH;
    LL.x = (s0[0] + s1[0]) * 0.5f;  LH.x = (s0[0] - s1[0]) * 0.5f;
    HL.x = (d0[0] + d1[0]) * 0.5f;  HH.x = (d0[0] - d1[0]) * 0.5f;
    LL.y = (s0[1] + s1[1]) * 0.5f;  LH.y = (s0[1] - s1[1]) * 0.5f;
    HL.y = (d0[1] + d1[1]) * 0.5f;  HH.y = (d0[1] - d1[1]) * 0.5f;
    LL.z = (s0[2] + s1[2]) * 0.5f;  LH.z = (s0[2] - s1[2]) * 0.5f;
    HL.z = (d0[2] + d1[2]) * 0.5f;  HH.z = (d0[2] - d1[2]) * 0.5f;
    LL.w = (s0[3] + s1[3]) * 0.5f;  LH.w = (s0[3] - s1[3]) * 0.5f;
    HL.w = (d0[3] + d1[3]) * 0.5f;  HH.w = (d0[3] - d1[3]) * 0.5f;

    // Output: plane (bc*4 + s), row i, cols 4q..4q+3
    size_t plane = (size_t)HO * WO;
    float* o = out + (size_t)(bc * 4) * plane + (size_t)i * WO + 4 * q;
    *(float4*)(o)             = LL;
    *(float4*)(o + plane)     = LH;
    *(float4*)(o + 2 * plane) = HL;
    *(float4*)(o + 3 * plane) = HH;
}

extern "C" void kernel_launch(void* const* d_in, const int* in_sizes, int n_in,
                              void* d_out, int out_size) {
    const float* x = (const float*)d_in[0];
    float* out = (float*)d_out;
    int total_threads = B_ * C_ * HO * QPW;   // 96 * 256 * 64 = 1,572,864
    int tpb = 256;
    int blocks = (total_threads + tpb - 1) / tpb;  // 6144
    haar_dwt2_kernel<<<blocks, tpb>>>(x, out);
}